// round 5
// baseline (speedup 1.0000x reference)
#include <cuda_runtime.h>

// Problem constants
#define BB 16
#define NN 4096
#define CC 512
#define HH 8
#define DD 64
#define HWDIM 64
__device__ __constant__ float kSCALE = 0.35355339059327379f; // 64^-0.25

// Scratch (device globals; allocation inside kernel_launch is forbidden)
__device__ float g_qkv[(size_t)BB * NN * 3 * CC];        // [65536, 1536]
__device__ float g_A[(size_t)BB * HH * HWDIM * HWDIM];   // row attn  [bh,64,64]
__device__ float g_Bm[(size_t)BB * HH * HWDIM * HWDIM];  // col attn  [bh,64,64]
__device__ float g_Vt[(size_t)BB * HH * DD * HWDIM * HWDIM]; // [bh, c, t, w]
__device__ float g_attnT[(size_t)BB * CC * NN];          // [b, C, N] channel-major

typedef unsigned long long u64;

__device__ __forceinline__ void ffma2(u64& d, u64 a, u64 b) {
    // packed fp32x2 FMA (Blackwell): d = a*b + d on both lanes
    asm("fma.rn.f32x2 %0, %1, %2, %0;" : "+l"(d) : "l"(a), "l"(b));
}
__device__ __forceinline__ float2 unpack2(u64 v) {
    float2 f;
    asm("mov.b64 {%0, %1}, %2;" : "=f"(f.x), "=f"(f.y) : "l"(v));
    return f;
}

// ---------------------------------------------------------------------------
// SGEMM NN: C[M,N] = A[M,K] @ B[K,N] + bias   (128x128 tile, BK=8, 256 thr)
// A tile staged DUPLICATED in smem so the micro-kernel runs on fma.rn.f32x2.
// ---------------------------------------------------------------------------
__global__ __launch_bounds__(256) void sgemm_nn(
    const float* __restrict__ A, const float* __restrict__ B,
    const float* __restrict__ bias, float* __restrict__ C,
    int N, int K)
{
    __shared__ __align__(16) float As2[8][256];  // dup: As2[k][2r]=As2[k][2r+1]=A[r]
    __shared__ __align__(16) float Bs[8][128];
    const int tid = threadIdx.x;
    const int m0 = blockIdx.y * 128;
    const int n0 = blockIdx.x * 128;

    const int arow = tid >> 1;            // 0..127
    const int acol = (tid & 1) * 4;       // 0 or 4
    const int brow = tid >> 5;            // 0..7
    const int bcol = (tid & 31) * 4;

    const int tx = tid & 15;
    const int ty = tid >> 4;

    const float* Aptr = A + (size_t)(m0 + arow) * K + acol;
    const float* Bptr = B + (size_t)brow * N + n0 + bcol;

    u64 acc2[8][4] = {};   // acc2[i][jp] = (acc[i][2jp], acc[i][2jp+1]); bits 0 == (0.f,0.f)

    for (int k0 = 0; k0 < K; k0 += 8) {
        float4 av = *(const float4*)(Aptr + k0);
        float4 bv = *(const float4*)(Bptr + (size_t)k0 * N);
        As2[acol + 0][2 * arow] = av.x; As2[acol + 0][2 * arow + 1] = av.x;
        As2[acol + 1][2 * arow] = av.y; As2[acol + 1][2 * arow + 1] = av.y;
        As2[acol + 2][2 * arow] = av.z; As2[acol + 2][2 * arow + 1] = av.z;
        As2[acol + 3][2 * arow] = av.w; As2[acol + 3][2 * arow + 1] = av.w;
        *(float4*)&Bs[brow][bcol] = bv;
        __syncthreads();
#pragma unroll
        for (int k = 0; k < 8; ++k) {
            u64 a2[8], b2[4];
            const ulonglong2* ap = (const ulonglong2*)&As2[k][ty * 16];
            const ulonglong2* bp = (const ulonglong2*)&Bs[k][tx * 8];
            ulonglong2 t0 = ap[0], t1 = ap[1], t2 = ap[2], t3 = ap[3];
            a2[0] = t0.x; a2[1] = t0.y; a2[2] = t1.x; a2[3] = t1.y;
            a2[4] = t2.x; a2[5] = t2.y; a2[6] = t3.x; a2[7] = t3.y;
            ulonglong2 u0 = bp[0], u1 = bp[1];
            b2[0] = u0.x; b2[1] = u0.y; b2[2] = u1.x; b2[3] = u1.y;
#pragma unroll
            for (int i = 0; i < 8; ++i)
#pragma unroll
                for (int jp = 0; jp < 4; ++jp)
                    ffma2(acc2[i][jp], a2[i], b2[jp]);
        }
        __syncthreads();
    }

    const float4 bia0 = *(const float4*)&bias[n0 + tx * 8];
    const float4 bia1 = *(const float4*)&bias[n0 + tx * 8 + 4];
#pragma unroll
    for (int i = 0; i < 8; ++i) {
        float* crow = C + (size_t)(m0 + ty * 8 + i) * N + n0 + tx * 8;
        float2 p0 = unpack2(acc2[i][0]);
        float2 p1 = unpack2(acc2[i][1]);
        float2 p2 = unpack2(acc2[i][2]);
        float2 p3 = unpack2(acc2[i][3]);
        float4 o0, o1;
        o0.x = p0.x + bia0.x; o0.y = p0.y + bia0.y;
        o0.z = p1.x + bia0.z; o0.w = p1.y + bia0.w;
        o1.x = p2.x + bia1.x; o1.y = p2.y + bia1.y;
        o1.z = p3.x + bia1.z; o1.w = p3.y + bia1.w;
        *(float4*)(crow + 0) = o0;
        *(float4*)(crow + 4) = o1;
    }
}

// ---------------------------------------------------------------------------
// SGEMM TN for projection: A stored channel-major per batch: g_attnT[b][k][ntok]
// C[m, n] = sum_k At[b(m)][k][ntok(m)] * B[k][n] + bias[n];  N = K = 512
// Same f32x2 micro-kernel with duplicated A staging.
// ---------------------------------------------------------------------------
__global__ __launch_bounds__(256) void sgemm_tn_proj(
    const float* __restrict__ At, const float* __restrict__ B,
    const float* __restrict__ bias, float* __restrict__ C)
{
    const int N = 512, K = 512;
    __shared__ __align__(16) float As2[8][256];
    __shared__ __align__(16) float Bs[8][128];
    const int tid = threadIdx.x;
    const int m0 = blockIdx.y * 128;
    const int n0 = blockIdx.x * 128;

    const int batch = m0 >> 12;      // m0 / 4096 (128 | 4096 so tiles don't cross)
    const int ntok0 = m0 & 4095;
    const float* Abase = At + (size_t)batch * CC * NN + ntok0;

    const int lk = tid >> 5;          // 0..7
    const int lm = (tid & 31) * 4;    // 0..124
    const int tx = tid & 15;
    const int ty = tid >> 4;

    u64 acc2[8][4] = {};

    for (int k0 = 0; k0 < K; k0 += 8) {
        float4 av = *(const float4*)(Abase + (size_t)(k0 + lk) * NN + lm);
        float4 bv = *(const float4*)(B + (size_t)(k0 + lk) * N + n0 + lm);
        *(float4*)&As2[lk][2 * lm + 0] = make_float4(av.x, av.x, av.y, av.y);
        *(float4*)&As2[lk][2 * lm + 4] = make_float4(av.z, av.z, av.w, av.w);
        *(float4*)&Bs[lk][lm] = bv;
        __syncthreads();
#pragma unroll
        for (int k = 0; k < 8; ++k) {
            u64 a2[8], b2[4];
            const ulonglong2* ap = (const ulonglong2*)&As2[k][ty * 16];
            const ulonglong2* bp = (const ulonglong2*)&Bs[k][tx * 8];
            ulonglong2 t0 = ap[0], t1 = ap[1], t2 = ap[2], t3 = ap[3];
            a2[0] = t0.x; a2[1] = t0.y; a2[2] = t1.x; a2[3] = t1.y;
            a2[4] = t2.x; a2[5] = t2.y; a2[6] = t3.x; a2[7] = t3.y;
            ulonglong2 u0 = bp[0], u1 = bp[1];
            b2[0] = u0.x; b2[1] = u0.y; b2[2] = u1.x; b2[3] = u1.y;
#pragma unroll
            for (int i = 0; i < 8; ++i)
#pragma unroll
                for (int jp = 0; jp < 4; ++jp)
                    ffma2(acc2[i][jp], a2[i], b2[jp]);
        }
        __syncthreads();
    }

    const float4 bia0 = *(const float4*)&bias[n0 + tx * 8];
    const float4 bia1 = *(const float4*)&bias[n0 + tx * 8 + 4];
#pragma unroll
    for (int i = 0; i < 8; ++i) {
        float* crow = C + (size_t)(m0 + ty * 8 + i) * N + n0 + tx * 8;
        float2 p0 = unpack2(acc2[i][0]);
        float2 p1 = unpack2(acc2[i][1]);
        float2 p2 = unpack2(acc2[i][2]);
        float2 p3 = unpack2(acc2[i][3]);
        float4 o0, o1;
        o0.x = p0.x + bia0.x; o0.y = p0.y + bia0.y;
        o0.z = p1.x + bia0.z; o0.w = p1.y + bia0.w;
        o1.x = p2.x + bia1.x; o1.y = p2.y + bia1.y;
        o1.z = p3.x + bia1.z; o1.w = p3.y + bia1.w;
        *(float4*)(crow + 0) = o0;
        *(float4*)(crow + 4) = o1;
    }
}

// ---------------------------------------------------------------------------
// Axial attention logits + softmax.
// colmode=0 (row attn): token = i*64 + chunk   (contract over w=chunk, d)
// colmode=1 (col attn): token = chunk*64 + i   (contract over t=chunk, d)
// out[bh][i][j] = softmax_j( SCALE * sum Q[i]. K[j] )
// ---------------------------------------------------------------------------
__global__ __launch_bounds__(256) void axial_logits_softmax(
    const float* __restrict__ qkv, float* __restrict__ out, int colmode)
{
    const int bh = blockIdx.x;
    const int b = bh >> 3, h = bh & 7;
    const float* qbase = qkv + (size_t)b * NN * (3 * CC) + h * 64;

    __shared__ float Qs[64][65];
    __shared__ float Ks[64][65];

    const int tid = threadIdx.x;
    const int tx = tid & 15;
    const int ty = tid >> 4;

    float acc[4][4] = {};

    for (int chunk = 0; chunk < 64; ++chunk) {
#pragma unroll
        for (int p = 0; p < 4; ++p) {
            int row = ty + p * 16;
            int token = colmode ? (chunk * 64 + row) : (row * 64 + chunk);
            const float* qp = qbase + (size_t)token * (3 * CC) + tx * 4;
            float4 q4 = *(const float4*)qp;
            float4 k4 = *(const float4*)(qp + CC);
            Qs[row][tx * 4 + 0] = q4.x; Qs[row][tx * 4 + 1] = q4.y;
            Qs[row][tx * 4 + 2] = q4.z; Qs[row][tx * 4 + 3] = q4.w;
            Ks[row][tx * 4 + 0] = k4.x; Ks[row][tx * 4 + 1] = k4.y;
            Ks[row][tx * 4 + 2] = k4.z; Ks[row][tx * 4 + 3] = k4.w;
        }
        __syncthreads();
#pragma unroll 16
        for (int k = 0; k < 64; ++k) {
            float qf[4], kf[4];
#pragma unroll
            for (int i = 0; i < 4; ++i) qf[i] = Qs[ty * 4 + i][k];
#pragma unroll
            for (int j = 0; j < 4; ++j) kf[j] = Ks[tx * 4 + j][k];
#pragma unroll
            for (int i = 0; i < 4; ++i)
#pragma unroll
                for (int j = 0; j < 4; ++j)
                    acc[i][j] += qf[i] * kf[j];
        }
        __syncthreads();
    }

    // write scaled logits back into Qs, then softmax over j
#pragma unroll
    for (int i = 0; i < 4; ++i)
#pragma unroll
        for (int j = 0; j < 4; ++j)
            Qs[ty * 4 + i][tx * 4 + j] = acc[i][j] * kSCALE;
    __syncthreads();

    const int warp = tid >> 5, lane = tid & 31;
    float* ob = out + (size_t)bh * 4096;
    for (int r = warp; r < 64; r += 8) {
        float v0 = Qs[r][lane], v1 = Qs[r][lane + 32];
        float m = fmaxf(v0, v1);
#pragma unroll
        for (int o = 16; o > 0; o >>= 1)
            m = fmaxf(m, __shfl_xor_sync(0xffffffffu, m, o));
        float e0 = __expf(v0 - m), e1 = __expf(v1 - m);
        float s = e0 + e1;
#pragma unroll
        for (int o = 16; o > 0; o >>= 1)
            s += __shfl_xor_sync(0xffffffffu, s, o);
        float inv = 1.0f / s;
        ob[r * 64 + lane] = e0 * inv;
        ob[r * 64 + lane + 32] = e1 * inv;
    }
}

// ---------------------------------------------------------------------------
// Transpose V: qkv v-part [token, h*64+c] -> Vt[bh][c][t][w]
// one block per (t, bh)
// ---------------------------------------------------------------------------
__global__ __launch_bounds__(256) void transpose_v(
    const float* __restrict__ qkv, float* __restrict__ Vt)
{
    const int t = blockIdx.x;
    const int bh = blockIdx.y;
    const int b = bh >> 3, h = bh & 7;
    __shared__ float tile[64][65];
    const int tid = threadIdx.x;
    const int tx = tid & 15, ty = tid >> 4;

    const float* vbase = qkv + (size_t)b * NN * (3 * CC) + 2 * CC + h * 64;
#pragma unroll
    for (int p = 0; p < 4; ++p) {
        int w = ty + p * 16;
        float4 v4 = *(const float4*)(vbase + (size_t)(t * 64 + w) * (3 * CC) + tx * 4);
        tile[w][tx * 4 + 0] = v4.x; tile[w][tx * 4 + 1] = v4.y;
        tile[w][tx * 4 + 2] = v4.z; tile[w][tx * 4 + 3] = v4.w;
    }
    __syncthreads();

    float* obase = Vt + (size_t)bh * 64 * 4096 + t * 64;
#pragma unroll
    for (int p = 0; p < 4; ++p) {
        int c = ty + p * 16;
        float4 o;
        o.x = tile[tx * 4 + 0][c];
        o.y = tile[tx * 4 + 1][c];
        o.z = tile[tx * 4 + 2][c];
        o.w = tile[tx * 4 + 3][c];
        *(float4*)(obase + (size_t)c * 4096 + tx * 4) = o;
    }
}

// ---------------------------------------------------------------------------
// Coupled combine: one block per (c, bh).
//   T1[t][u] = sum_w Vc[t][w] * bm[u][w]
//   O[i][w]  = sum_j a[i][j] * T1[j][w]
// write O to attnT[b][h*64+c][i*64+w]  (== attnT[(bh*64+c)*4096 + ...])
// ---------------------------------------------------------------------------
__global__ __launch_bounds__(256) void combine_kernel(
    const float* __restrict__ Abuf, const float* __restrict__ Bmbuf,
    const float* __restrict__ Vt, float* __restrict__ attnT)
{
    extern __shared__ float sm[];
    float (*As_)[65] = reinterpret_cast<float (*)[65]>(sm);
    float (*Bs_)[65] = reinterpret_cast<float (*)[65]>(sm + 64 * 65);
    float (*Vs)[65]  = reinterpret_cast<float (*)[65]>(sm + 2 * 64 * 65);
    float (*Ts)[65]  = reinterpret_cast<float (*)[65]>(sm + 3 * 64 * 65);

    const int c = blockIdx.x;
    const int bh = blockIdx.y;
    const int tid = threadIdx.x;
    const int tx = tid & 15, ty = tid >> 4;

    const float* ab = Abuf + (size_t)bh * 4096;
    const float* bb = Bmbuf + (size_t)bh * 4096;
    const float* vb = Vt + ((size_t)bh * 64 + c) * 4096;

#pragma unroll
    for (int p = 0; p < 4; ++p) {
        int row = ty + p * 16;
        float4 a4 = *(const float4*)(ab + row * 64 + tx * 4);
        float4 b4 = *(const float4*)(bb + row * 64 + tx * 4);
        float4 v4 = *(const float4*)(vb + row * 64 + tx * 4);
        As_[row][tx * 4 + 0] = a4.x; As_[row][tx * 4 + 1] = a4.y;
        As_[row][tx * 4 + 2] = a4.z; As_[row][tx * 4 + 3] = a4.w;
        Bs_[row][tx * 4 + 0] = b4.x; Bs_[row][tx * 4 + 1] = b4.y;
        Bs_[row][tx * 4 + 2] = b4.z; Bs_[row][tx * 4 + 3] = b4.w;
        Vs[row][tx * 4 + 0] = v4.x; Vs[row][tx * 4 + 1] = v4.y;
        Vs[row][tx * 4 + 2] = v4.z; Vs[row][tx * 4 + 3] = v4.w;
    }
    __syncthreads();

    // phase 1: T1 = Vc @ bm^T
    {
        float acc[4][4] = {};
#pragma unroll 16
        for (int w = 0; w < 64; ++w) {
            float vf[4], bf[4];
#pragma unroll
            for (int i = 0; i < 4; ++i) vf[i] = Vs[ty * 4 + i][w];
#pragma unroll
            for (int j = 0; j < 4; ++j) bf[j] = Bs_[tx * 4 + j][w];
#pragma unroll
            for (int i = 0; i < 4; ++i)
#pragma unroll
                for (int j = 0; j < 4; ++j)
                    acc[i][j] += vf[i] * bf[j];
        }
#pragma unroll
        for (int i = 0; i < 4; ++i)
#pragma unroll
            for (int j = 0; j < 4; ++j)
                Ts[ty * 4 + i][tx * 4 + j] = acc[i][j];
    }
    __syncthreads();

    // phase 2: O = a @ T1
    float acc[4][4] = {};
#pragma unroll 16
    for (int j = 0; j < 64; ++j) {
        float af[4], tf[4];
#pragma unroll
        for (int i = 0; i < 4; ++i) af[i] = As_[ty * 4 + i][j];
#pragma unroll
        for (int jj = 0; jj < 4; ++jj) tf[jj] = Ts[j][tx * 4 + jj];
#pragma unroll
        for (int i = 0; i < 4; ++i)
#pragma unroll
            for (int jj = 0; jj < 4; ++jj)
                acc[i][jj] += af[i] * tf[jj];
    }

    float* ob = attnT + ((size_t)bh * 64 + c) * 4096;
#pragma unroll
    for (int i = 0; i < 4; ++i) {
        float4 o;
        o.x = acc[i][0]; o.y = acc[i][1]; o.z = acc[i][2]; o.w = acc[i][3];
        *(float4*)(ob + (ty * 4 + i) * 64 + tx * 4) = o;
    }
}

// ---------------------------------------------------------------------------
extern "C" void kernel_launch(void* const* d_in, const int* in_sizes, int n_in,
                              void* d_out, int out_size)
{
    const float* x     = (const float*)d_in[0];
    const float* Wqkv  = (const float*)d_in[1];
    const float* bqkv  = (const float*)d_in[2];
    const float* Wproj = (const float*)d_in[3];
    const float* bproj = (const float*)d_in[4];
    float* out = (float*)d_out;

    float *qkv, *Ab, *Bmb, *Vt, *attnT;
    cudaGetSymbolAddress((void**)&qkv, g_qkv);
    cudaGetSymbolAddress((void**)&Ab, g_A);
    cudaGetSymbolAddress((void**)&Bmb, g_Bm);
    cudaGetSymbolAddress((void**)&Vt, g_Vt);
    cudaGetSymbolAddress((void**)&attnT, g_attnT);

    // 1. QKV projection: [65536,512] @ [512,1536]
    sgemm_nn<<<dim3(1536 / 128, (BB * NN) / 128), 256>>>(x, Wqkv, bqkv, qkv, 3 * CC, CC);

    // 2+3. axial attentions (row / col), softmaxed
    axial_logits_softmax<<<BB * HH, 256>>>(qkv, Ab, 0);
    axial_logits_softmax<<<BB * HH, 256>>>(qkv, Bmb, 1);

    // 4. transpose V to channel-major
    transpose_v<<<dim3(64, BB * HH), 256>>>(qkv, Vt);

    // 5. coupled combine -> attnT [B, C, N]
    cudaFuncSetAttribute(combine_kernel, cudaFuncAttributeMaxDynamicSharedMemorySize,
                         4 * 64 * 65 * sizeof(float));
    combine_kernel<<<dim3(64, BB * HH), 256, 4 * 64 * 65 * sizeof(float)>>>(Ab, Bmb, Vt, attnT);

    // 6. projection: attnT^T @ Wproj + bproj -> out [B,N,C]
    sgemm_tn_proj<<<dim3(512 / 128, (BB * NN) / 128), 256>>>(attnT, Wproj, bproj, out);
}

// round 9
// speedup vs baseline: 2.1242x; 2.1242x over previous
#include <cuda_runtime.h>
#include <cuda_bf16.h>
#include <cstdint>

// Problem constants
#define BB 16
#define NN 4096
#define CC 512
#define HH 8
#define DD 64
#define HWDIM 64
__device__ __constant__ float kSCALE = 0.35355339059327379f; // 64^-0.25

// ---------------------------------------------------------------------------
// Scratch (device globals; allocation inside kernel_launch is forbidden)
// ---------------------------------------------------------------------------
__device__ float g_qkv[(size_t)BB * NN * 3 * CC];            // [65536, 1536]
__device__ float g_A[(size_t)BB * HH * HWDIM * HWDIM];       // row attn  [bh,64,64]
__device__ float g_Bm[(size_t)BB * HH * HWDIM * HWDIM];      // col attn  [bh,64,64]
__device__ float g_Vt[(size_t)BB * HH * DD * HWDIM * HWDIM]; // [bh, c, t, w]
__device__ float g_attnT[(size_t)BB * CC * NN];              // [b, C, N]

// bf16 split buffers (g_Xh/g_Xl reused for attn-output before proj GEMM)
__device__ __align__(16) __nv_bfloat16 g_Xh[(size_t)BB * NN * CC];
__device__ __align__(16) __nv_bfloat16 g_Xl[(size_t)BB * NN * CC];
__device__ __align__(16) __nv_bfloat16 g_WqTh[(size_t)3 * CC * CC];
__device__ __align__(16) __nv_bfloat16 g_WqTl[(size_t)3 * CC * CC];
__device__ __align__(16) __nv_bfloat16 g_WpTh[(size_t)CC * CC];
__device__ __align__(16) __nv_bfloat16 g_WpTl[(size_t)CC * CC];

// ---------------------------------------------------------------------------
// mma.sync m16n8k16 bf16 (row.col, fp32 accum) — sm_80+, safe at sm_103 target
// ---------------------------------------------------------------------------
__device__ __forceinline__ void mma16816(float* c, const uint32_t* a, const uint32_t* b)
{
    asm volatile(
        "mma.sync.aligned.m16n8k16.row.col.f32.bf16.bf16.f32 "
        "{%0,%1,%2,%3}, {%4,%5,%6,%7}, {%8,%9}, {%0,%1,%2,%3};"
        : "+f"(c[0]), "+f"(c[1]), "+f"(c[2]), "+f"(c[3])
        : "r"(a[0]), "r"(a[1]), "r"(a[2]), "r"(a[3]), "r"(b[0]), "r"(b[1]));
}

// ---------------------------------------------------------------------------
// fp32 -> (bf16 hi, bf16 lo) elementwise split; n4 float4 groups
// ---------------------------------------------------------------------------
__global__ __launch_bounds__(256) void split_f32(
    const float* __restrict__ in, __nv_bfloat16* __restrict__ hi,
    __nv_bfloat16* __restrict__ lo, int n4)
{
    int i = blockIdx.x * 256 + threadIdx.x;
    if (i >= n4) return;
    float4 v = ((const float4*)in)[i];
    __nv_bfloat16 h0 = __float2bfloat16(v.x);
    __nv_bfloat16 h1 = __float2bfloat16(v.y);
    __nv_bfloat16 h2 = __float2bfloat16(v.z);
    __nv_bfloat16 h3 = __float2bfloat16(v.w);
    __nv_bfloat16 l0 = __float2bfloat16(v.x - __bfloat162float(h0));
    __nv_bfloat16 l1 = __float2bfloat16(v.y - __bfloat162float(h1));
    __nv_bfloat16 l2 = __float2bfloat16(v.z - __bfloat162float(h2));
    __nv_bfloat16 l3 = __float2bfloat16(v.w - __bfloat162float(h3));
    __nv_bfloat162 hp0 = __halves2bfloat162(h0, h1);
    __nv_bfloat162 hp1 = __halves2bfloat162(h2, h3);
    __nv_bfloat162 lp0 = __halves2bfloat162(l0, l1);
    __nv_bfloat162 lp1 = __halves2bfloat162(l2, l3);
    uint2 hv, lv;
    hv.x = *(uint32_t*)&hp0; hv.y = *(uint32_t*)&hp1;
    lv.x = *(uint32_t*)&lp0; lv.y = *(uint32_t*)&lp1;
    ((uint2*)hi)[i] = hv;
    ((uint2*)lo)[i] = lv;
}

// ---------------------------------------------------------------------------
// Split + transpose weights: W[K=512][Nw] fp32 -> WT_h/WT_l [Nw][512] bf16
// block (32,8), grid (Nw/32, 512/32)
// ---------------------------------------------------------------------------
__global__ void split_transpose_w(
    const float* __restrict__ W, __nv_bfloat16* __restrict__ Th,
    __nv_bfloat16* __restrict__ Tl, int Nw)
{
    __shared__ float tile[32][33];
    const int n0 = blockIdx.x * 32, k0 = blockIdx.y * 32;
    const int tx = threadIdx.x, ty = threadIdx.y;
#pragma unroll
    for (int i = 0; i < 4; ++i)
        tile[ty + i * 8][tx] = W[(size_t)(k0 + ty + i * 8) * Nw + n0 + tx];
    __syncthreads();
#pragma unroll
    for (int i = 0; i < 4; ++i) {
        float v = tile[tx][ty + i * 8];
        __nv_bfloat16 h = __float2bfloat16(v);
        __nv_bfloat16 l = __float2bfloat16(v - __bfloat162float(h));
        size_t o = (size_t)(n0 + ty + i * 8) * 512 + k0 + tx;
        Th[o] = h; Tl[o] = l;
    }
}

// ---------------------------------------------------------------------------
// Split + transpose attn output: attnT[b][c][tok] fp32 -> Y[b][tok][c] bf16 h/l
// block (32,8), grid (4096/32, 512/32, 16)
// ---------------------------------------------------------------------------
__global__ void split_transpose_attn(
    const float* __restrict__ in, __nv_bfloat16* __restrict__ Yh,
    __nv_bfloat16* __restrict__ Yl)
{
    __shared__ float tile[32][33];
    const int tok0 = blockIdx.x * 32, c0 = blockIdx.y * 32, b = blockIdx.z;
    const int tx = threadIdx.x, ty = threadIdx.y;
    const float* ib = in + (size_t)b * CC * NN + (size_t)c0 * NN + tok0;
#pragma unroll
    for (int i = 0; i < 4; ++i)
        tile[ty + i * 8][tx] = ib[(size_t)(ty + i * 8) * NN + tx];
    __syncthreads();
    __nv_bfloat16* yh = Yh + (size_t)b * NN * CC;
    __nv_bfloat16* yl = Yl + (size_t)b * NN * CC;
#pragma unroll
    for (int i = 0; i < 4; ++i) {
        float v = tile[tx][ty + i * 8];
        __nv_bfloat16 h = __float2bfloat16(v);
        __nv_bfloat16 l = __float2bfloat16(v - __bfloat162float(h));
        size_t o = (size_t)(tok0 + ty + i * 8) * 512 + c0 + tx;
        yh[o] = h; yl[o] = l;
    }
}

// ---------------------------------------------------------------------------
// HMMA bf16x3-split GEMM: C[M][Ntot] = (Ah+Al)[M][512] @ (Bh+Bl)^T + bias
// A: [M][512] bf16 K-major. BT: [Ntot][512] bf16 (N rows of K).
// CTA 128x128, 8 warps (4M x 2N), warp tile 32x64, K chunks of 64.
// Per chunk: 3 products (Ah*Bh + Ah*Bl + Al*Bh) into fp32 mma accumulators.
// smem rows padded to 72 bf16 (144B) -> conflict-free fragment LDS.
// ---------------------------------------------------------------------------
#define SPAD 72
#define TILE_B (128 * SPAD * 2)              // bytes per bf16 tile (18432)
#define GEMM_SMEM_BYTES (4 * TILE_B)         // 73728

__global__ __launch_bounds__(256, 1) void gemm_bf16x3(
    const __nv_bfloat16* __restrict__ Ah, const __nv_bfloat16* __restrict__ Al,
    const __nv_bfloat16* __restrict__ BhT, const __nv_bfloat16* __restrict__ BlT,
    const float* __restrict__ bias, float* __restrict__ Cc, int Ntot)
{
    extern __shared__ __align__(16) char smem[];
    __nv_bfloat16* sAh = (__nv_bfloat16*)(smem);
    __nv_bfloat16* sAl = (__nv_bfloat16*)(smem + TILE_B);
    __nv_bfloat16* sBh = (__nv_bfloat16*)(smem + 2 * TILE_B);
    __nv_bfloat16* sBl = (__nv_bfloat16*)(smem + 3 * TILE_B);

    const int tid = threadIdx.x;
    const int wid = tid >> 5, lane = tid & 31;
    const int wm = wid >> 1, wn = wid & 1;       // 4 x 2 warp grid
    const int quad = lane >> 2, tq = lane & 3;
    const int m0 = blockIdx.y * 128, n0 = blockIdx.x * 128;

    // staging assignment: 4 groups of 64 threads, one 128x64 tile each
    const int grp = tid >> 6;
    const int gtid = tid & 63;
    const __nv_bfloat16* src =
        (grp == 0) ? Ah + (size_t)m0 * 512 :
        (grp == 1) ? Al + (size_t)m0 * 512 :
        (grp == 2) ? BhT + (size_t)n0 * 512 :
                     BlT + (size_t)n0 * 512;
    __nv_bfloat16* dstt =
        (grp == 0) ? sAh : (grp == 1) ? sAl : (grp == 2) ? sBh : sBl;

    float acc[2][8][4] = {};   // [m-tile][n-tile][frag]

    const __nv_bfloat16* wAh = sAh + (wm * 32) * SPAD;
    const __nv_bfloat16* wAl = sAl + (wm * 32) * SPAD;
    const __nv_bfloat16* wBh = sBh + (wn * 64) * SPAD;
    const __nv_bfloat16* wBl = sBl + (wn * 64) * SPAD;

    for (int ch = 0; ch < 8; ++ch) {
        const int k0 = ch * 64;
        // stage: 128 rows x 64 bf16 (128B) per tile, row stride 144B
#pragma unroll
        for (int i = 0; i < 16; ++i) {
            int idx = gtid + 64 * i;          // 0..1023
            int row = idx >> 3;               // 0..127
            int c16 = idx & 7;                // 16B chunk within the 128B row
            uint4 v = *(const uint4*)(src + (size_t)row * 512 + k0 + c16 * 8);
            *(uint4*)(dstt + row * SPAD + c16 * 8) = v;
        }
        __syncthreads();

#pragma unroll
        for (int ks = 0; ks < 4; ++ks) {
            const int kb = ks * 16 + tq * 2;  // bf16 col of this thread's frag
            uint32_t ah[2][4], al[2][4], bh[8][2], bl[8][2];
#pragma unroll
            for (int mt = 0; mt < 2; ++mt) {
                const int r0 = mt * 16 + quad, r1 = r0 + 8;
                ah[mt][0] = *(const uint32_t*)(wAh + r0 * SPAD + kb);
                ah[mt][1] = *(const uint32_t*)(wAh + r1 * SPAD + kb);
                ah[mt][2] = *(const uint32_t*)(wAh + r0 * SPAD + kb + 8);
                ah[mt][3] = *(const uint32_t*)(wAh + r1 * SPAD + kb + 8);
                al[mt][0] = *(const uint32_t*)(wAl + r0 * SPAD + kb);
                al[mt][1] = *(const uint32_t*)(wAl + r1 * SPAD + kb);
                al[mt][2] = *(const uint32_t*)(wAl + r0 * SPAD + kb + 8);
                al[mt][3] = *(const uint32_t*)(wAl + r1 * SPAD + kb + 8);
            }
#pragma unroll
            for (int nt = 0; nt < 8; ++nt) {
                const int nr = nt * 8 + quad;
                bh[nt][0] = *(const uint32_t*)(wBh + nr * SPAD + kb);
                bh[nt][1] = *(const uint32_t*)(wBh + nr * SPAD + kb + 8);
                bl[nt][0] = *(const uint32_t*)(wBl + nr * SPAD + kb);
                bl[nt][1] = *(const uint32_t*)(wBl + nr * SPAD + kb + 8);
            }
#pragma unroll
            for (int mt = 0; mt < 2; ++mt)
#pragma unroll
                for (int nt = 0; nt < 8; ++nt) {
                    mma16816(acc[mt][nt], ah[mt], bh[nt]);
                    mma16816(acc[mt][nt], ah[mt], bl[nt]);
                    mma16816(acc[mt][nt], al[mt], bh[nt]);
                }
        }
        __syncthreads();
    }

    // epilogue: fragment layout c0,c1 -> (row, col..col+1); c2,c3 -> (row+8, ..)
#pragma unroll
    for (int mt = 0; mt < 2; ++mt) {
        const int row = m0 + wm * 32 + mt * 16 + quad;
#pragma unroll
        for (int nt = 0; nt < 8; ++nt) {
            const int col = n0 + wn * 64 + nt * 8 + tq * 2;
            const float b0 = bias[col], b1 = bias[col + 1];
            float2 v0, v1;
            v0.x = acc[mt][nt][0] + b0; v0.y = acc[mt][nt][1] + b1;
            v1.x = acc[mt][nt][2] + b0; v1.y = acc[mt][nt][3] + b1;
            *(float2*)(Cc + (size_t)row * Ntot + col) = v0;
            *(float2*)(Cc + (size_t)(row + 8) * Ntot + col) = v1;
        }
    }
}

// ---------------------------------------------------------------------------
// Axial attention logits + softmax (unchanged from best passing version)
// ---------------------------------------------------------------------------
__global__ __launch_bounds__(256) void axial_logits_softmax(
    const float* __restrict__ qkv, float* __restrict__ out, int colmode)
{
    const int bh = blockIdx.x;
    const int b = bh >> 3, h = bh & 7;
    const float* qbase = qkv + (size_t)b * NN * (3 * CC) + h * 64;

    __shared__ float Qs[64][65];
    __shared__ float Ks[64][65];

    const int tid = threadIdx.x;
    const int tx = tid & 15;
    const int ty = tid >> 4;

    float acc[4][4] = {};

    for (int chunk = 0; chunk < 64; ++chunk) {
#pragma unroll
        for (int p = 0; p < 4; ++p) {
            int row = ty + p * 16;
            int token = colmode ? (chunk * 64 + row) : (row * 64 + chunk);
            const float* qp = qbase + (size_t)token * (3 * CC) + tx * 4;
            float4 q4 = *(const float4*)qp;
            float4 k4 = *(const float4*)(qp + CC);
            Qs[row][tx * 4 + 0] = q4.x; Qs[row][tx * 4 + 1] = q4.y;
            Qs[row][tx * 4 + 2] = q4.z; Qs[row][tx * 4 + 3] = q4.w;
            Ks[row][tx * 4 + 0] = k4.x; Ks[row][tx * 4 + 1] = k4.y;
            Ks[row][tx * 4 + 2] = k4.z; Ks[row][tx * 4 + 3] = k4.w;
        }
        __syncthreads();
#pragma unroll 16
        for (int k = 0; k < 64; ++k) {
            float qf[4], kf[4];
#pragma unroll
            for (int i = 0; i < 4; ++i) qf[i] = Qs[ty * 4 + i][k];
#pragma unroll
            for (int j = 0; j < 4; ++j) kf[j] = Ks[tx * 4 + j][k];
#pragma unroll
            for (int i = 0; i < 4; ++i)
#pragma unroll
                for (int j = 0; j < 4; ++j)
                    acc[i][j] += qf[i] * kf[j];
        }
        __syncthreads();
    }

#pragma unroll
    for (int i = 0; i < 4; ++i)
#pragma unroll
        for (int j = 0; j < 4; ++j)
            Qs[ty * 4 + i][tx * 4 + j] = acc[i][j] * kSCALE;
    __syncthreads();

    const int warp = tid >> 5, lane = tid & 31;
    float* ob = out + (size_t)bh * 4096;
    for (int r = warp; r < 64; r += 8) {
        float v0 = Qs[r][lane], v1 = Qs[r][lane + 32];
        float m = fmaxf(v0, v1);
#pragma unroll
        for (int o = 16; o > 0; o >>= 1)
            m = fmaxf(m, __shfl_xor_sync(0xffffffffu, m, o));
        float e0 = __expf(v0 - m), e1 = __expf(v1 - m);
        float s = e0 + e1;
#pragma unroll
        for (int o = 16; o > 0; o >>= 1)
            s += __shfl_xor_sync(0xffffffffu, s, o);
        float inv = 1.0f / s;
        ob[r * 64 + lane] = e0 * inv;
        ob[r * 64 + lane + 32] = e1 * inv;
    }
}

// ---------------------------------------------------------------------------
// Transpose V: qkv v-part [token, h*64+c] -> Vt[bh][c][t][w]  (unchanged)
// ---------------------------------------------------------------------------
__global__ __launch_bounds__(256) void transpose_v(
    const float* __restrict__ qkv, float* __restrict__ Vt)
{
    const int t = blockIdx.x;
    const int bh = blockIdx.y;
    const int b = bh >> 3, h = bh & 7;
    __shared__ float tile[64][65];
    const int tid = threadIdx.x;
    const int tx = tid & 15, ty = tid >> 4;

    const float* vbase = qkv + (size_t)b * NN * (3 * CC) + 2 * CC + h * 64;
#pragma unroll
    for (int p = 0; p < 4; ++p) {
        int w = ty + p * 16;
        float4 v4 = *(const float4*)(vbase + (size_t)(t * 64 + w) * (3 * CC) + tx * 4);
        tile[w][tx * 4 + 0] = v4.x; tile[w][tx * 4 + 1] = v4.y;
        tile[w][tx * 4 + 2] = v4.z; tile[w][tx * 4 + 3] = v4.w;
    }
    __syncthreads();

    float* obase = Vt + (size_t)bh * 64 * 4096 + t * 64;
#pragma unroll
    for (int p = 0; p < 4; ++p) {
        int c = ty + p * 16;
        float4 o;
        o.x = tile[tx * 4 + 0][c];
        o.y = tile[tx * 4 + 1][c];
        o.z = tile[tx * 4 + 2][c];
        o.w = tile[tx * 4 + 3][c];
        *(float4*)(obase + (size_t)c * 4096 + tx * 4) = o;
    }
}

// ---------------------------------------------------------------------------
// Coupled combine (unchanged): one block per (c, bh).
// ---------------------------------------------------------------------------
__global__ __launch_bounds__(256) void combine_kernel(
    const float* __restrict__ Abuf, const float* __restrict__ Bmbuf,
    const float* __restrict__ Vt, float* __restrict__ attnT)
{
    extern __shared__ float sm[];
    float (*As_)[65] = reinterpret_cast<float (*)[65]>(sm);
    float (*Bs_)[65] = reinterpret_cast<float (*)[65]>(sm + 64 * 65);
    float (*Vs)[65]  = reinterpret_cast<float (*)[65]>(sm + 2 * 64 * 65);
    float (*Ts)[65]  = reinterpret_cast<float (*)[65]>(sm + 3 * 64 * 65);

    const int c = blockIdx.x;
    const int bh = blockIdx.y;
    const int tid = threadIdx.x;
    const int tx = tid & 15, ty = tid >> 4;

    const float* ab = Abuf + (size_t)bh * 4096;
    const float* bb = Bmbuf + (size_t)bh * 4096;
    const float* vb = Vt + ((size_t)bh * 64 + c) * 4096;

#pragma unroll
    for (int p = 0; p < 4; ++p) {
        int row = ty + p * 16;
        float4 a4 = *(const float4*)(ab + row * 64 + tx * 4);
        float4 b4 = *(const float4*)(bb + row * 64 + tx * 4);
        float4 v4 = *(const float4*)(vb + row * 64 + tx * 4);
        As_[row][tx * 4 + 0] = a4.x; As_[row][tx * 4 + 1] = a4.y;
        As_[row][tx * 4 + 2] = a4.z; As_[row][tx * 4 + 3] = a4.w;
        Bs_[row][tx * 4 + 0] = b4.x; Bs_[row][tx * 4 + 1] = b4.y;
        Bs_[row][tx * 4 + 2] = b4.z; Bs_[row][tx * 4 + 3] = b4.w;
        Vs[row][tx * 4 + 0] = v4.x; Vs[row][tx * 4 + 1] = v4.y;
        Vs[row][tx * 4 + 2] = v4.z; Vs[row][tx * 4 + 3] = v4.w;
    }
    __syncthreads();

    {
        float acc[4][4] = {};
#pragma unroll 16
        for (int w = 0; w < 64; ++w) {
            float vf[4], bf[4];
#pragma unroll
            for (int i = 0; i < 4; ++i) vf[i] = Vs[ty * 4 + i][w];
#pragma unroll
            for (int j = 0; j < 4; ++j) bf[j] = Bs_[tx * 4 + j][w];
#pragma unroll
            for (int i = 0; i < 4; ++i)
#pragma unroll
                for (int j = 0; j < 4; ++j)
                    acc[i][j] += vf[i] * bf[j];
        }
#pragma unroll
        for (int i = 0; i < 4; ++i)
#pragma unroll
            for (int j = 0; j < 4; ++j)
                Ts[ty * 4 + i][tx * 4 + j] = acc[i][j];
    }
    __syncthreads();

    float acc[4][4] = {};
#pragma unroll 16
    for (int j = 0; j < 64; ++j) {
        float af[4], tf[4];
#pragma unroll
        for (int i = 0; i < 4; ++i) af[i] = As_[ty * 4 + i][j];
#pragma unroll
        for (int jj = 0; jj < 4; ++jj) tf[jj] = Ts[j][tx * 4 + jj];
#pragma unroll
        for (int i = 0; i < 4; ++i)
#pragma unroll
            for (int jj = 0; jj < 4; ++jj)
                acc[i][jj] += af[i] * tf[jj];
    }

    float* ob = attnT + ((size_t)bh * 64 + c) * 4096;
#pragma unroll
    for (int i = 0; i < 4; ++i) {
        float4 o;
        o.x = acc[i][0]; o.y = acc[i][1]; o.z = acc[i][2]; o.w = acc[i][3];
        *(float4*)(ob + (ty * 4 + i) * 64 + tx * 4) = o;
    }
}

// ---------------------------------------------------------------------------
extern "C" void kernel_launch(void* const* d_in, const int* in_sizes, int n_in,
                              void* d_out, int out_size)
{
    const float* x     = (const float*)d_in[0];
    const float* Wqkv  = (const float*)d_in[1];
    const float* bqkv  = (const float*)d_in[2];
    const float* Wproj = (const float*)d_in[3];
    const float* bproj = (const float*)d_in[4];
    float* out = (float*)d_out;

    float *qkv, *Ab, *Bmb, *Vt, *attnT;
    __nv_bfloat16 *Xh, *Xl, *WqTh, *WqTl, *WpTh, *WpTl;
    cudaGetSymbolAddress((void**)&qkv, g_qkv);
    cudaGetSymbolAddress((void**)&Ab, g_A);
    cudaGetSymbolAddress((void**)&Bmb, g_Bm);
    cudaGetSymbolAddress((void**)&Vt, g_Vt);
    cudaGetSymbolAddress((void**)&attnT, g_attnT);
    cudaGetSymbolAddress((void**)&Xh, g_Xh);
    cudaGetSymbolAddress((void**)&Xl, g_Xl);
    cudaGetSymbolAddress((void**)&WqTh, g_WqTh);
    cudaGetSymbolAddress((void**)&WqTl, g_WqTl);
    cudaGetSymbolAddress((void**)&WpTh, g_WpTh);
    cudaGetSymbolAddress((void**)&WpTl, g_WpTl);

    // host-side attribute sets (capture-safe; proven in R3)
    cudaFuncSetAttribute(gemm_bf16x3, cudaFuncAttributeMaxDynamicSharedMemorySize,
                         GEMM_SMEM_BYTES);
    cudaFuncSetAttribute(combine_kernel, cudaFuncAttributeMaxDynamicSharedMemorySize,
                         4 * 64 * 65 * sizeof(float));

    // 0. split inputs to bf16 hi/lo
    split_f32<<<(BB * NN * CC / 4 + 255) / 256, 256>>>(x, Xh, Xl, BB * NN * CC / 4);
    split_transpose_w<<<dim3(1536 / 32, 512 / 32), dim3(32, 8)>>>(Wqkv, WqTh, WqTl, 1536);
    split_transpose_w<<<dim3(512 / 32, 512 / 32), dim3(32, 8)>>>(Wproj, WpTh, WpTl, 512);

    // 1. QKV projection on tensor cores: [65536,512] x [512,1536]
    gemm_bf16x3<<<dim3(1536 / 128, (BB * NN) / 128), 256, GEMM_SMEM_BYTES>>>(
        Xh, Xl, WqTh, WqTl, bqkv, qkv, 1536);

    // 2+3. axial attentions (row / col), softmaxed
    axial_logits_softmax<<<BB * HH, 256>>>(qkv, Ab, 0);
    axial_logits_softmax<<<BB * HH, 256>>>(qkv, Bmb, 1);

    // 4. transpose V to channel-major
    transpose_v<<<dim3(64, BB * HH), 256>>>(qkv, Vt);

    // 5. coupled combine -> attnT [B, C, N]
    combine_kernel<<<dim3(64, BB * HH), 256, 4 * 64 * 65 * sizeof(float)>>>(Ab, Bmb, Vt, attnT);

    // 6. split+transpose attn output to token-major bf16 (reuse Xh/Xl)
    split_transpose_attn<<<dim3(NN / 32, CC / 32, BB), dim3(32, 8)>>>(attnT, Xh, Xl);

    // 7. projection on tensor cores: [65536,512] x [512,512]
    gemm_bf16x3<<<dim3(512 / 128, (BB * NN) / 128), 256, GEMM_SMEM_BYTES>>>(
        Xh, Xl, WpTh, WpTl, bproj, out, 512);
}

// round 10
// speedup vs baseline: 2.3910x; 1.1256x over previous
#include <cuda_runtime.h>
#include <cuda_bf16.h>
#include <cstdint>

// Problem constants
#define BB 16
#define NN 4096
#define CC 512
#define HH 8
#define DD 64
#define HWDIM 64
__device__ __constant__ float kSCALE = 0.35355339059327379f; // 64^-0.25

// ---------------------------------------------------------------------------
// Scratch (device globals; allocation inside kernel_launch is forbidden)
// ---------------------------------------------------------------------------
__device__ float g_qkv[(size_t)BB * NN * 3 * CC];            // [65536, 1536]
__device__ float g_A[(size_t)BB * HH * HWDIM * HWDIM];       // row attn  [bh,64,64]
__device__ float g_Bm[(size_t)BB * HH * HWDIM * HWDIM];      // col attn  [bh,64,64]
__device__ float g_Vt[(size_t)BB * HH * DD * HWDIM * HWDIM]; // [bh, c, t, w]
__device__ float g_attnT[(size_t)BB * CC * NN];              // [b, C, N]

// bf16 split buffers (g_Xh/g_Xl reused for attn-output before proj GEMM)
__device__ __align__(16) __nv_bfloat16 g_Xh[(size_t)BB * NN * CC];
__device__ __align__(16) __nv_bfloat16 g_Xl[(size_t)BB * NN * CC];
__device__ __align__(16) __nv_bfloat16 g_WqTh[(size_t)3 * CC * CC];
__device__ __align__(16) __nv_bfloat16 g_WqTl[(size_t)3 * CC * CC];
__device__ __align__(16) __nv_bfloat16 g_WpTh[(size_t)CC * CC];
__device__ __align__(16) __nv_bfloat16 g_WpTl[(size_t)CC * CC];

// ---------------------------------------------------------------------------
// mma.sync m16n8k16 bf16 (row.col, fp32 accum) — sm_80+, safe at sm_103 target
// ---------------------------------------------------------------------------
__device__ __forceinline__ void mma16816(float* c, const uint32_t* a, const uint32_t* b)
{
    asm volatile(
        "mma.sync.aligned.m16n8k16.row.col.f32.bf16.bf16.f32 "
        "{%0,%1,%2,%3}, {%4,%5,%6,%7}, {%8,%9}, {%0,%1,%2,%3};"
        : "+f"(c[0]), "+f"(c[1]), "+f"(c[2]), "+f"(c[3])
        : "r"(a[0]), "r"(a[1]), "r"(a[2]), "r"(a[3]), "r"(b[0]), "r"(b[1]));
}
__device__ __forceinline__ uint32_t smem_u32(const void* p) {
    uint32_t a;
    asm("{ .reg .u64 t; cvta.to.shared.u64 t, %1; cvt.u32.u64 %0, t; }"
        : "=r"(a) : "l"(p));
    return a;
}
__device__ __forceinline__ void cp_async16(uint32_t dst, const void* src) {
    asm volatile("cp.async.cg.shared.global [%0], [%1], 16;" :: "r"(dst), "l"(src));
}

// ---------------------------------------------------------------------------
// fp32 -> (bf16 hi, bf16 lo) elementwise split; n4 float4 groups
// ---------------------------------------------------------------------------
__global__ __launch_bounds__(256) void split_f32(
    const float* __restrict__ in, __nv_bfloat16* __restrict__ hi,
    __nv_bfloat16* __restrict__ lo, int n4)
{
    int i = blockIdx.x * 256 + threadIdx.x;
    if (i >= n4) return;
    float4 v = ((const float4*)in)[i];
    __nv_bfloat16 h0 = __float2bfloat16(v.x);
    __nv_bfloat16 h1 = __float2bfloat16(v.y);
    __nv_bfloat16 h2 = __float2bfloat16(v.z);
    __nv_bfloat16 h3 = __float2bfloat16(v.w);
    __nv_bfloat16 l0 = __float2bfloat16(v.x - __bfloat162float(h0));
    __nv_bfloat16 l1 = __float2bfloat16(v.y - __bfloat162float(h1));
    __nv_bfloat16 l2 = __float2bfloat16(v.z - __bfloat162float(h2));
    __nv_bfloat16 l3 = __float2bfloat16(v.w - __bfloat162float(h3));
    __nv_bfloat162 hp0 = __halves2bfloat162(h0, h1);
    __nv_bfloat162 hp1 = __halves2bfloat162(h2, h3);
    __nv_bfloat162 lp0 = __halves2bfloat162(l0, l1);
    __nv_bfloat162 lp1 = __halves2bfloat162(l2, l3);
    uint2 hv, lv;
    hv.x = *(uint32_t*)&hp0; hv.y = *(uint32_t*)&hp1;
    lv.x = *(uint32_t*)&lp0; lv.y = *(uint32_t*)&lp1;
    ((uint2*)hi)[i] = hv;
    ((uint2*)lo)[i] = lv;
}

// ---------------------------------------------------------------------------
// Split + transpose weights: W[K=512][Nw] fp32 -> WT_h/WT_l [Nw][512] bf16
// ---------------------------------------------------------------------------
__global__ void split_transpose_w(
    const float* __restrict__ W, __nv_bfloat16* __restrict__ Th,
    __nv_bfloat16* __restrict__ Tl, int Nw)
{
    __shared__ float tile[32][33];
    const int n0 = blockIdx.x * 32, k0 = blockIdx.y * 32;
    const int tx = threadIdx.x, ty = threadIdx.y;
#pragma unroll
    for (int i = 0; i < 4; ++i)
        tile[ty + i * 8][tx] = W[(size_t)(k0 + ty + i * 8) * Nw + n0 + tx];
    __syncthreads();
#pragma unroll
    for (int i = 0; i < 4; ++i) {
        float v = tile[tx][ty + i * 8];
        __nv_bfloat16 h = __float2bfloat16(v);
        __nv_bfloat16 l = __float2bfloat16(v - __bfloat162float(h));
        size_t o = (size_t)(n0 + ty + i * 8) * 512 + k0 + tx;
        Th[o] = h; Tl[o] = l;
    }
}

// ---------------------------------------------------------------------------
// Split + transpose attn output: attnT[b][c][tok] fp32 -> Y[b][tok][c] bf16 h/l
// ---------------------------------------------------------------------------
__global__ void split_transpose_attn(
    const float* __restrict__ in, __nv_bfloat16* __restrict__ Yh,
    __nv_bfloat16* __restrict__ Yl)
{
    __shared__ float tile[32][33];
    const int tok0 = blockIdx.x * 32, c0 = blockIdx.y * 32, b = blockIdx.z;
    const int tx = threadIdx.x, ty = threadIdx.y;
    const float* ib = in + (size_t)b * CC * NN + (size_t)c0 * NN + tok0;
#pragma unroll
    for (int i = 0; i < 4; ++i)
        tile[ty + i * 8][tx] = ib[(size_t)(ty + i * 8) * NN + tx];
    __syncthreads();
    __nv_bfloat16* yh = Yh + (size_t)b * NN * CC;
    __nv_bfloat16* yl = Yl + (size_t)b * NN * CC;
#pragma unroll
    for (int i = 0; i < 4; ++i) {
        float v = tile[tx][ty + i * 8];
        __nv_bfloat16 h = __float2bfloat16(v);
        __nv_bfloat16 l = __float2bfloat16(v - __bfloat162float(h));
        size_t o = (size_t)(tok0 + ty + i * 8) * 512 + c0 + tx;
        yh[o] = h; yl[o] = l;
    }
}

// ---------------------------------------------------------------------------
// HMMA bf16x3-split GEMM, double-buffered with cp.async.
// C[M][Ntot] = (Ah+Al)[M][512] @ (Bh+Bl)^T + bias
// CTA 128x128, 8 warps (4M x 2N), warp tile 32x64, K chunks of 64.
// Per chunk: 3 products (Ah*Bh + Ah*Bl + Al*Bh) into fp32 mma accumulators.
// smem rows padded to 72 bf16 (144B) -> conflict-free fragment LDS.
// Two buffers of 4 tiles; cp.async fills chunk ch+1 while MMAs run on ch.
// ---------------------------------------------------------------------------
#define SPAD 72
#define TILE_B (128 * SPAD * 2)              // bytes per bf16 tile (18432)
#define BUF_B (4 * TILE_B)                   // one buffer: 73728
#define GEMM_SMEM_BYTES (2 * BUF_B)          // 147456

__global__ __launch_bounds__(256, 1) void gemm_bf16x3(
    const __nv_bfloat16* __restrict__ Ah, const __nv_bfloat16* __restrict__ Al,
    const __nv_bfloat16* __restrict__ BhT, const __nv_bfloat16* __restrict__ BlT,
    const float* __restrict__ bias, float* __restrict__ Cc, int Ntot)
{
    extern __shared__ __align__(16) char smem[];

    const int tid = threadIdx.x;
    const int wid = tid >> 5, lane = tid & 31;
    const int wm = wid >> 1, wn = wid & 1;       // 4 x 2 warp grid
    const int quad = lane >> 2, tq = lane & 3;
    const int m0 = blockIdx.y * 128, n0 = blockIdx.x * 128;

    // staging assignment: 4 groups of 64 threads, one 128x64 tile each
    const int grp = tid >> 6;
    const int gtid = tid & 63;
    const __nv_bfloat16* src =
        (grp == 0) ? Ah + (size_t)m0 * 512 :
        (grp == 1) ? Al + (size_t)m0 * 512 :
        (grp == 2) ? BhT + (size_t)n0 * 512 :
                     BlT + (size_t)n0 * 512;

    const uint32_t sb = smem_u32(smem);
    const uint32_t dbase0 = sb + grp * TILE_B;          // this group's tile, buf0
    // per-thread element offsets (row, 16B chunk) are fixed across chunks
    const int row_ = gtid >> 3;        // base rows gtid>>3 + 8*i? no:
    // idx = gtid + 64*i -> row = idx>>3, c16 = idx&7

    // prologue: issue chunk 0 into buffer 0
    {
        const __nv_bfloat16* s = src;
#pragma unroll
        for (int i = 0; i < 16; ++i) {
            int idx = gtid + 64 * i;
            int row = idx >> 3, c16 = idx & 7;
            cp_async16(dbase0 + row * 144 + c16 * 16, s + (size_t)row * 512 + c16 * 8);
        }
        asm volatile("cp.async.commit_group;" ::: "memory");
    }

    float acc[2][8][4] = {};   // [m-tile][n-tile][frag]

    for (int ch = 0; ch < 8; ++ch) {
        const int bi = ch & 1;
        // issue next chunk into the other buffer
        if (ch < 7) {
            const __nv_bfloat16* s = src + (ch + 1) * 64;
            const uint32_t db = dbase0 + ((ch + 1) & 1) * BUF_B;
#pragma unroll
            for (int i = 0; i < 16; ++i) {
                int idx = gtid + 64 * i;
                int row = idx >> 3, c16 = idx & 7;
                cp_async16(db + row * 144 + c16 * 16, s + (size_t)row * 512 + c16 * 8);
            }
            asm volatile("cp.async.commit_group;" ::: "memory");
            asm volatile("cp.async.wait_group 1;" ::: "memory");
        } else {
            asm volatile("cp.async.wait_group 0;" ::: "memory");
        }
        __syncthreads();

        const char* cb = smem + bi * BUF_B;
        const __nv_bfloat16* wAh = (const __nv_bfloat16*)(cb) + (wm * 32) * SPAD;
        const __nv_bfloat16* wAl = (const __nv_bfloat16*)(cb + TILE_B) + (wm * 32) * SPAD;
        const __nv_bfloat16* wBh = (const __nv_bfloat16*)(cb + 2 * TILE_B) + (wn * 64) * SPAD;
        const __nv_bfloat16* wBl = (const __nv_bfloat16*)(cb + 3 * TILE_B) + (wn * 64) * SPAD;

#pragma unroll
        for (int ks = 0; ks < 4; ++ks) {
            const int kb = ks * 16 + tq * 2;  // bf16 col of this thread's frag
            uint32_t ah[2][4], al[2][4], bh[8][2], bl[8][2];
#pragma unroll
            for (int mt = 0; mt < 2; ++mt) {
                const int r0 = mt * 16 + quad, r1 = r0 + 8;
                ah[mt][0] = *(const uint32_t*)(wAh + r0 * SPAD + kb);
                ah[mt][1] = *(const uint32_t*)(wAh + r1 * SPAD + kb);
                ah[mt][2] = *(const uint32_t*)(wAh + r0 * SPAD + kb + 8);
                ah[mt][3] = *(const uint32_t*)(wAh + r1 * SPAD + kb + 8);
                al[mt][0] = *(const uint32_t*)(wAl + r0 * SPAD + kb);
                al[mt][1] = *(const uint32_t*)(wAl + r1 * SPAD + kb);
                al[mt][2] = *(const uint32_t*)(wAl + r0 * SPAD + kb + 8);
                al[mt][3] = *(const uint32_t*)(wAl + r1 * SPAD + kb + 8);
            }
#pragma unroll
            for (int nt = 0; nt < 8; ++nt) {
                const int nr = nt * 8 + quad;
                bh[nt][0] = *(const uint32_t*)(wBh + nr * SPAD + kb);
                bh[nt][1] = *(const uint32_t*)(wBh + nr * SPAD + kb + 8);
                bl[nt][0] = *(const uint32_t*)(wBl + nr * SPAD + kb);
                bl[nt][1] = *(const uint32_t*)(wBl + nr * SPAD + kb + 8);
            }
#pragma unroll
            for (int mt = 0; mt < 2; ++mt)
#pragma unroll
                for (int nt = 0; nt < 8; ++nt) {
                    mma16816(acc[mt][nt], ah[mt], bh[nt]);
                    mma16816(acc[mt][nt], ah[mt], bl[nt]);
                    mma16816(acc[mt][nt], al[mt], bh[nt]);
                }
        }
        __syncthreads();
    }

    // epilogue: fragment layout c0,c1 -> (row, col..col+1); c2,c3 -> (row+8, ..)
#pragma unroll
    for (int mt = 0; mt < 2; ++mt) {
        const int row = m0 + wm * 32 + mt * 16 + quad;
#pragma unroll
        for (int nt = 0; nt < 8; ++nt) {
            const int col = n0 + wn * 64 + nt * 8 + tq * 2;
            const float b0 = bias[col], b1 = bias[col + 1];
            float2 v0, v1;
            v0.x = acc[mt][nt][0] + b0; v0.y = acc[mt][nt][1] + b1;
            v1.x = acc[mt][nt][2] + b0; v1.y = acc[mt][nt][3] + b1;
            *(float2*)(Cc + (size_t)row * Ntot + col) = v0;
            *(float2*)(Cc + (size_t)(row + 8) * Ntot + col) = v1;
        }
    }
}

// ---------------------------------------------------------------------------
// Axial attention logits + softmax. Row and col modes FUSED in one launch:
// blockIdx.y == 0 -> row attn -> outA; ==1 -> col attn -> outB.
// ---------------------------------------------------------------------------
__global__ __launch_bounds__(256) void axial_logits_softmax(
    const float* __restrict__ qkv, float* __restrict__ outA,
    float* __restrict__ outB)
{
    const int bh = blockIdx.x;
    const int colmode = blockIdx.y;
    const int b = bh >> 3, h = bh & 7;
    const float* qbase = qkv + (size_t)b * NN * (3 * CC) + h * 64;

    __shared__ float Qs[64][65];
    __shared__ float Ks[64][65];

    const int tid = threadIdx.x;
    const int tx = tid & 15;
    const int ty = tid >> 4;

    float acc[4][4] = {};

    for (int chunk = 0; chunk < 64; ++chunk) {
#pragma unroll
        for (int p = 0; p < 4; ++p) {
            int row = ty + p * 16;
            int token = colmode ? (chunk * 64 + row) : (row * 64 + chunk);
            const float* qp = qbase + (size_t)token * (3 * CC) + tx * 4;
            float4 q4 = *(const float4*)qp;
            float4 k4 = *(const float4*)(qp + CC);
            Qs[row][tx * 4 + 0] = q4.x; Qs[row][tx * 4 + 1] = q4.y;
            Qs[row][tx * 4 + 2] = q4.z; Qs[row][tx * 4 + 3] = q4.w;
            Ks[row][tx * 4 + 0] = k4.x; Ks[row][tx * 4 + 1] = k4.y;
            Ks[row][tx * 4 + 2] = k4.z; Ks[row][tx * 4 + 3] = k4.w;
        }
        __syncthreads();
#pragma unroll 16
        for (int k = 0; k < 64; ++k) {
            float qf[4], kf[4];
#pragma unroll
            for (int i = 0; i < 4; ++i) qf[i] = Qs[ty * 4 + i][k];
#pragma unroll
            for (int j = 0; j < 4; ++j) kf[j] = Ks[tx * 4 + j][k];
#pragma unroll
            for (int i = 0; i < 4; ++i)
#pragma unroll
                for (int j = 0; j < 4; ++j)
                    acc[i][j] += qf[i] * kf[j];
        }
        __syncthreads();
    }

#pragma unroll
    for (int i = 0; i < 4; ++i)
#pragma unroll
        for (int j = 0; j < 4; ++j)
            Qs[ty * 4 + i][tx * 4 + j] = acc[i][j] * kSCALE;
    __syncthreads();

    const int warp = tid >> 5, lane = tid & 31;
    float* ob = (colmode ? outB : outA) + (size_t)bh * 4096;
    for (int r = warp; r < 64; r += 8) {
        float v0 = Qs[r][lane], v1 = Qs[r][lane + 32];
        float m = fmaxf(v0, v1);
#pragma unroll
        for (int o = 16; o > 0; o >>= 1)
            m = fmaxf(m, __shfl_xor_sync(0xffffffffu, m, o));
        float e0 = __expf(v0 - m), e1 = __expf(v1 - m);
        float s = e0 + e1;
#pragma unroll
        for (int o = 16; o > 0; o >>= 1)
            s += __shfl_xor_sync(0xffffffffu, s, o);
        float inv = 1.0f / s;
        ob[r * 64 + lane] = e0 * inv;
        ob[r * 64 + lane + 32] = e1 * inv;
    }
}

// ---------------------------------------------------------------------------
// Transpose V: qkv v-part [token, h*64+c] -> Vt[bh][c][t][w]
// ---------------------------------------------------------------------------
__global__ __launch_bounds__(256) void transpose_v(
    const float* __restrict__ qkv, float* __restrict__ Vt)
{
    const int t = blockIdx.x;
    const int bh = blockIdx.y;
    const int b = bh >> 3, h = bh & 7;
    __shared__ float tile[64][65];
    const int tid = threadIdx.x;
    const int tx = tid & 15, ty = tid >> 4;

    const float* vbase = qkv + (size_t)b * NN * (3 * CC) + 2 * CC + h * 64;
#pragma unroll
    for (int p = 0; p < 4; ++p) {
        int w = ty + p * 16;
        float4 v4 = *(const float4*)(vbase + (size_t)(t * 64 + w) * (3 * CC) + tx * 4);
        tile[w][tx * 4 + 0] = v4.x; tile[w][tx * 4 + 1] = v4.y;
        tile[w][tx * 4 + 2] = v4.z; tile[w][tx * 4 + 3] = v4.w;
    }
    __syncthreads();

    float* obase = Vt + (size_t)bh * 64 * 4096 + t * 64;
#pragma unroll
    for (int p = 0; p < 4; ++p) {
        int c = ty + p * 16;
        float4 o;
        o.x = tile[tx * 4 + 0][c];
        o.y = tile[tx * 4 + 1][c];
        o.z = tile[tx * 4 + 2][c];
        o.w = tile[tx * 4 + 3][c];
        *(float4*)(obase + (size_t)c * 4096 + tx * 4) = o;
    }
}

// ---------------------------------------------------------------------------
// Coupled combine: one block per (c, bh).
// ---------------------------------------------------------------------------
__global__ __launch_bounds__(256) void combine_kernel(
    const float* __restrict__ Abuf, const float* __restrict__ Bmbuf,
    const float* __restrict__ Vt, float* __restrict__ attnT)
{
    extern __shared__ float sm[];
    float (*As_)[65] = reinterpret_cast<float (*)[65]>(sm);
    float (*Bs_)[65] = reinterpret_cast<float (*)[65]>(sm + 64 * 65);
    float (*Vs)[65]  = reinterpret_cast<float (*)[65]>(sm + 2 * 64 * 65);
    float (*Ts)[65]  = reinterpret_cast<float (*)[65]>(sm + 3 * 64 * 65);

    const int c = blockIdx.x;
    const int bh = blockIdx.y;
    const int tid = threadIdx.x;
    const int tx = tid & 15, ty = tid >> 4;

    const float* ab = Abuf + (size_t)bh * 4096;
    const float* bb = Bmbuf + (size_t)bh * 4096;
    const float* vb = Vt + ((size_t)bh * 64 + c) * 4096;

#pragma unroll
    for (int p = 0; p < 4; ++p) {
        int row = ty + p * 16;
        float4 a4 = *(const float4*)(ab + row * 64 + tx * 4);
        float4 b4 = *(const float4*)(bb + row * 64 + tx * 4);
        float4 v4 = *(const float4*)(vb + row * 64 + tx * 4);
        As_[row][tx * 4 + 0] = a4.x; As_[row][tx * 4 + 1] = a4.y;
        As_[row][tx * 4 + 2] = a4.z; As_[row][tx * 4 + 3] = a4.w;
        Bs_[row][tx * 4 + 0] = b4.x; Bs_[row][tx * 4 + 1] = b4.y;
        Bs_[row][tx * 4 + 2] = b4.z; Bs_[row][tx * 4 + 3] = b4.w;
        Vs[row][tx * 4 + 0] = v4.x; Vs[row][tx * 4 + 1] = v4.y;
        Vs[row][tx * 4 + 2] = v4.z; Vs[row][tx * 4 + 3] = v4.w;
    }
    __syncthreads();

    {
        float acc[4][4] = {};
#pragma unroll 16
        for (int w = 0; w < 64; ++w) {
            float vf[4], bf[4];
#pragma unroll
            for (int i = 0; i < 4; ++i) vf[i] = Vs[ty * 4 + i][w];
#pragma unroll
            for (int j = 0; j < 4; ++j) bf[j] = Bs_[tx * 4 + j][w];
#pragma unroll
            for (int i = 0; i < 4; ++i)
#pragma unroll
                for (int j = 0; j < 4; ++j)
                    acc[i][j] += vf[i] * bf[j];
        }
#pragma unroll
        for (int i = 0; i < 4; ++i)
#pragma unroll
            for (int j = 0; j < 4; ++j)
                Ts[ty * 4 + i][tx * 4 + j] = acc[i][j];
    }
    __syncthreads();

    float acc[4][4] = {};
#pragma unroll 16
    for (int j = 0; j < 64; ++j) {
        float af[4], tf[4];
#pragma unroll
        for (int i = 0; i < 4; ++i) af[i] = As_[ty * 4 + i][j];
#pragma unroll
        for (int jj = 0; jj < 4; ++jj) tf[jj] = Ts[j][tx * 4 + jj];
#pragma unroll
        for (int i = 0; i < 4; ++i)
#pragma unroll
            for (int jj = 0; jj < 4; ++jj)
                acc[i][jj] += af[i] * tf[jj];
    }

    float* ob = attnT + ((size_t)bh * 64 + c) * 4096;
#pragma unroll
    for (int i = 0; i < 4; ++i) {
        float4 o;
        o.x = acc[i][0]; o.y = acc[i][1]; o.z = acc[i][2]; o.w = acc[i][3];
        *(float4*)(ob + (ty * 4 + i) * 64 + tx * 4) = o;
    }
}

// ---------------------------------------------------------------------------
extern "C" void kernel_launch(void* const* d_in, const int* in_sizes, int n_in,
                              void* d_out, int out_size)
{
    const float* x     = (const float*)d_in[0];
    const float* Wqkv  = (const float*)d_in[1];
    const float* bqkv  = (const float*)d_in[2];
    const float* Wproj = (const float*)d_in[3];
    const float* bproj = (const float*)d_in[4];
    float* out = (float*)d_out;

    float *qkv, *Ab, *Bmb, *Vt, *attnT;
    __nv_bfloat16 *Xh, *Xl, *WqTh, *WqTl, *WpTh, *WpTl;
    cudaGetSymbolAddress((void**)&qkv, g_qkv);
    cudaGetSymbolAddress((void**)&Ab, g_A);
    cudaGetSymbolAddress((void**)&Bmb, g_Bm);
    cudaGetSymbolAddress((void**)&Vt, g_Vt);
    cudaGetSymbolAddress((void**)&attnT, g_attnT);
    cudaGetSymbolAddress((void**)&Xh, g_Xh);
    cudaGetSymbolAddress((void**)&Xl, g_Xl);
    cudaGetSymbolAddress((void**)&WqTh, g_WqTh);
    cudaGetSymbolAddress((void**)&WqTl, g_WqTl);
    cudaGetSymbolAddress((void**)&WpTh, g_WpTh);
    cudaGetSymbolAddress((void**)&WpTl, g_WpTl);

    // host-side attribute sets (capture-safe; proven)
    cudaFuncSetAttribute(gemm_bf16x3, cudaFuncAttributeMaxDynamicSharedMemorySize,
                         GEMM_SMEM_BYTES);
    cudaFuncSetAttribute(combine_kernel, cudaFuncAttributeMaxDynamicSharedMemorySize,
                         4 * 64 * 65 * sizeof(float));

    // 0. split inputs to bf16 hi/lo
    split_f32<<<(BB * NN * CC / 4 + 255) / 256, 256>>>(x, Xh, Xl, BB * NN * CC / 4);
    split_transpose_w<<<dim3(1536 / 32, 512 / 32), dim3(32, 8)>>>(Wqkv, WqTh, WqTl, 1536);
    split_transpose_w<<<dim3(512 / 32, 512 / 32), dim3(32, 8)>>>(Wproj, WpTh, WpTl, 512);

    // 1. QKV projection on tensor cores: [65536,512] x [512,1536]
    gemm_bf16x3<<<dim3(1536 / 128, (BB * NN) / 128), 256, GEMM_SMEM_BYTES>>>(
        Xh, Xl, WqTh, WqTl, bqkv, qkv, 1536);

    // 2+3. axial attentions (row + col fused in one launch), softmaxed
    axial_logits_softmax<<<dim3(BB * HH, 2), 256>>>(qkv, Ab, Bmb);

    // 4. transpose V to channel-major
    transpose_v<<<dim3(64, BB * HH), 256>>>(qkv, Vt);

    // 5. coupled combine -> attnT [B, C, N]
    combine_kernel<<<dim3(64, BB * HH), 256, 4 * 64 * 65 * sizeof(float)>>>(Ab, Bmb, Vt, attnT);

    // 6. split+transpose attn output to token-major bf16 (reuse Xh/Xl)
    split_transpose_attn<<<dim3(NN / 32, CC / 32, BB), dim3(32, 8)>>>(attnT, Xh, Xl);

    // 7. projection on tensor cores: [65536,512] x [512,512]
    gemm_bf16x3<<<dim3(512 / 128, (BB * NN) / 128), 256, GEMM_SMEM_BYTES>>>(
        Xh, Xl, WpTh, WpTl, bproj, out, 512);
}

// round 11
// speedup vs baseline: 2.7029x; 1.1305x over previous
#include <cuda_runtime.h>
#include <cuda_bf16.h>
#include <cstdint>

// Problem constants
#define BB 16
#define NN 4096
#define CC 512
#define HH 8
#define DD 64
#define HWDIM 64
__device__ __constant__ float kSCALE = 0.35355339059327379f; // 64^-0.25

// ---------------------------------------------------------------------------
// Scratch (device globals; allocation inside kernel_launch is forbidden)
// ---------------------------------------------------------------------------
__device__ float g_qkv[(size_t)BB * NN * 3 * CC];            // [65536, 1536]
__device__ float g_A[(size_t)BB * HH * HWDIM * HWDIM];       // row attn  [bh,64,64]
__device__ float g_Bm[(size_t)BB * HH * HWDIM * HWDIM];      // col attn  [bh,64,64]
__device__ float g_Vt[(size_t)BB * HH * DD * HWDIM * HWDIM]; // [bh, c, t, w]
__device__ float g_attnT[(size_t)BB * CC * NN];              // [b, C, N]

// bf16 split buffers (g_Xh/g_Xl reused for attn-output before proj GEMM)
__device__ __align__(16) __nv_bfloat16 g_Xh[(size_t)BB * NN * CC];
__device__ __align__(16) __nv_bfloat16 g_Xl[(size_t)BB * NN * CC];
__device__ __align__(16) __nv_bfloat16 g_WqTh[(size_t)3 * CC * CC];
__device__ __align__(16) __nv_bfloat16 g_WqTl[(size_t)3 * CC * CC];
__device__ __align__(16) __nv_bfloat16 g_WpTh[(size_t)CC * CC];
__device__ __align__(16) __nv_bfloat16 g_WpTl[(size_t)CC * CC];

// ---------------------------------------------------------------------------
// helpers
// ---------------------------------------------------------------------------
__device__ __forceinline__ void mma16816(float* c, const uint32_t* a, const uint32_t* b)
{
    asm volatile(
        "mma.sync.aligned.m16n8k16.row.col.f32.bf16.bf16.f32 "
        "{%0,%1,%2,%3}, {%4,%5,%6,%7}, {%8,%9}, {%0,%1,%2,%3};"
        : "+f"(c[0]), "+f"(c[1]), "+f"(c[2]), "+f"(c[3])
        : "r"(a[0]), "r"(a[1]), "r"(a[2]), "r"(a[3]), "r"(b[0]), "r"(b[1]));
}
__device__ __forceinline__ uint32_t smem_u32(const void* p) {
    uint32_t a;
    asm("{ .reg .u64 t; cvta.to.shared.u64 t, %1; cvt.u32.u64 %0, t; }"
        : "=r"(a) : "l"(p));
    return a;
}
__device__ __forceinline__ void cp_async16(uint32_t dst, const void* src) {
    asm volatile("cp.async.cg.shared.global [%0], [%1], 16;" :: "r"(dst), "l"(src));
}
// swizzled smem read: tile rows are 128B (8 x 16B chunks), chunk XOR (row&7)
__device__ __forceinline__ uint32_t lds_sw(const char* tile, int row, int chunk, int boff) {
    return *(const uint32_t*)(tile + row * 128 + (((chunk) ^ (row & 7)) << 4) + boff);
}

// ---------------------------------------------------------------------------
// fp32 -> (bf16 hi, bf16 lo) elementwise split; n4 float4 groups
// ---------------------------------------------------------------------------
__global__ __launch_bounds__(256) void split_f32(
    const float* __restrict__ in, __nv_bfloat16* __restrict__ hi,
    __nv_bfloat16* __restrict__ lo, int n4)
{
    int i = blockIdx.x * 256 + threadIdx.x;
    if (i >= n4) return;
    float4 v = ((const float4*)in)[i];
    __nv_bfloat16 h0 = __float2bfloat16(v.x);
    __nv_bfloat16 h1 = __float2bfloat16(v.y);
    __nv_bfloat16 h2 = __float2bfloat16(v.z);
    __nv_bfloat16 h3 = __float2bfloat16(v.w);
    __nv_bfloat16 l0 = __float2bfloat16(v.x - __bfloat162float(h0));
    __nv_bfloat16 l1 = __float2bfloat16(v.y - __bfloat162float(h1));
    __nv_bfloat16 l2 = __float2bfloat16(v.z - __bfloat162float(h2));
    __nv_bfloat16 l3 = __float2bfloat16(v.w - __bfloat162float(h3));
    __nv_bfloat162 hp0 = __halves2bfloat162(h0, h1);
    __nv_bfloat162 hp1 = __halves2bfloat162(h2, h3);
    __nv_bfloat162 lp0 = __halves2bfloat162(l0, l1);
    __nv_bfloat162 lp1 = __halves2bfloat162(l2, l3);
    uint2 hv, lv;
    hv.x = *(uint32_t*)&hp0; hv.y = *(uint32_t*)&hp1;
    lv.x = *(uint32_t*)&lp0; lv.y = *(uint32_t*)&lp1;
    ((uint2*)hi)[i] = hv;
    ((uint2*)lo)[i] = lv;
}

// ---------------------------------------------------------------------------
// Split + transpose weights: W[K=512][Nw] fp32 -> WT_h/WT_l [Nw][512] bf16
// ---------------------------------------------------------------------------
__global__ void split_transpose_w(
    const float* __restrict__ W, __nv_bfloat16* __restrict__ Th,
    __nv_bfloat16* __restrict__ Tl, int Nw)
{
    __shared__ float tile[32][33];
    const int n0 = blockIdx.x * 32, k0 = blockIdx.y * 32;
    const int tx = threadIdx.x, ty = threadIdx.y;
#pragma unroll
    for (int i = 0; i < 4; ++i)
        tile[ty + i * 8][tx] = W[(size_t)(k0 + ty + i * 8) * Nw + n0 + tx];
    __syncthreads();
#pragma unroll
    for (int i = 0; i < 4; ++i) {
        float v = tile[tx][ty + i * 8];
        __nv_bfloat16 h = __float2bfloat16(v);
        __nv_bfloat16 l = __float2bfloat16(v - __bfloat162float(h));
        size_t o = (size_t)(n0 + ty + i * 8) * 512 + k0 + tx;
        Th[o] = h; Tl[o] = l;
    }
}

// ---------------------------------------------------------------------------
// Split + transpose attn output: attnT[b][c][tok] fp32 -> Y[b][tok][c] bf16 h/l
// ---------------------------------------------------------------------------
__global__ void split_transpose_attn(
    const float* __restrict__ in, __nv_bfloat16* __restrict__ Yh,
    __nv_bfloat16* __restrict__ Yl)
{
    __shared__ float tile[32][33];
    const int tok0 = blockIdx.x * 32, c0 = blockIdx.y * 32, b = blockIdx.z;
    const int tx = threadIdx.x, ty = threadIdx.y;
    const float* ib = in + (size_t)b * CC * NN + (size_t)c0 * NN + tok0;
#pragma unroll
    for (int i = 0; i < 4; ++i)
        tile[ty + i * 8][tx] = ib[(size_t)(ty + i * 8) * NN + tx];
    __syncthreads();
    __nv_bfloat16* yh = Yh + (size_t)b * NN * CC;
    __nv_bfloat16* yl = Yl + (size_t)b * NN * CC;
#pragma unroll
    for (int i = 0; i < 4; ++i) {
        float v = tile[tx][ty + i * 8];
        __nv_bfloat16 h = __float2bfloat16(v);
        __nv_bfloat16 l = __float2bfloat16(v - __bfloat162float(h));
        size_t o = (size_t)(tok0 + ty + i * 8) * 512 + c0 + tx;
        yh[o] = h; yl[o] = l;
    }
}

// ---------------------------------------------------------------------------
// HMMA bf16x3-split GEMM, XOR-swizzled smem, single buffer, 2 CTAs/SM.
// C[M][Ntot] = (Ah+Al)[M][512] @ (Bh+Bl)^T + bias
// CTA 128x128, 8 warps (4M x 2N), warp tile 32x64, K chunks of 64.
// Tiles: 128 rows x 128B, swizzle chunk^=(row&7) -> conflict-free frag LDS.
// Cross-CTA overlap (2 resident CTAs) hides the staging phases.
// ---------------------------------------------------------------------------
#define TILE_B 16384                          // 128 rows * 128B
#define GEMM_SMEM_BYTES (4 * TILE_B)          // 65536 -> 2 CTAs/SM

__global__ __launch_bounds__(256, 2) void gemm_bf16x3(
    const __nv_bfloat16* __restrict__ Ah, const __nv_bfloat16* __restrict__ Al,
    const __nv_bfloat16* __restrict__ BhT, const __nv_bfloat16* __restrict__ BlT,
    const float* __restrict__ bias, float* __restrict__ Cc, int Ntot)
{
    extern __shared__ __align__(16) char smem[];
    char* tAh = smem;
    char* tAl = smem + TILE_B;
    char* tBh = smem + 2 * TILE_B;
    char* tBl = smem + 3 * TILE_B;

    const int tid = threadIdx.x;
    const int wid = tid >> 5, lane = tid & 31;
    const int wm = wid >> 1, wn = wid & 1;       // 4 x 2 warp grid
    const int quad = lane >> 2, tq = lane & 3;
    const int boff = tq * 4;                     // byte offset within 16B chunk
    const int m0 = blockIdx.y * 128, n0 = blockIdx.x * 128;

    // staging assignment: 4 groups of 64 threads, one 128x64-bf16 tile each
    const int grp = tid >> 6;
    const int gtid = tid & 63;
    const __nv_bfloat16* src =
        (grp == 0) ? Ah + (size_t)m0 * 512 :
        (grp == 1) ? Al + (size_t)m0 * 512 :
        (grp == 2) ? BhT + (size_t)n0 * 512 :
                     BlT + (size_t)n0 * 512;
    const uint32_t dt = smem_u32(smem) + grp * TILE_B;

    float acc[2][8][4] = {};   // [m-tile][n-tile][frag]

    for (int ch = 0; ch < 8; ++ch) {
        // stage chunk ch (swizzled)
#pragma unroll
        for (int i = 0; i < 16; ++i) {
            int idx = gtid + 64 * i;          // 0..1023
            int row = idx >> 3;               // 0..127
            int c16 = idx & 7;                // 16B chunk within the 128B row
            cp_async16(dt + row * 128 + ((c16 ^ (row & 7)) << 4),
                       src + (size_t)row * 512 + ch * 64 + c16 * 8);
        }
        asm volatile("cp.async.commit_group;" ::: "memory");
        asm volatile("cp.async.wait_group 0;" ::: "memory");
        __syncthreads();

        const int ra = wm * 32;               // A row base for this warp
        const int rb = wn * 64;               // B row base for this warp

#pragma unroll
        for (int ks = 0; ks < 4; ++ks) {
            const int c0_ = 2 * ks, c1_ = 2 * ks + 1;
            uint32_t ah[2][4], al[2][4];
#pragma unroll
            for (int mt = 0; mt < 2; ++mt) {
                const int r0 = ra + mt * 16 + quad, r1 = r0 + 8;
                ah[mt][0] = lds_sw(tAh, r0, c0_, boff);
                ah[mt][1] = lds_sw(tAh, r1, c0_, boff);
                ah[mt][2] = lds_sw(tAh, r0, c1_, boff);
                ah[mt][3] = lds_sw(tAh, r1, c1_, boff);
                al[mt][0] = lds_sw(tAl, r0, c0_, boff);
                al[mt][1] = lds_sw(tAl, r1, c0_, boff);
                al[mt][2] = lds_sw(tAl, r0, c1_, boff);
                al[mt][3] = lds_sw(tAl, r1, c1_, boff);
            }
#pragma unroll
            for (int nt = 0; nt < 8; ++nt) {
                const int nr = rb + nt * 8 + quad;
                uint32_t bh[2], bl[2];
                bh[0] = lds_sw(tBh, nr, c0_, boff);
                bh[1] = lds_sw(tBh, nr, c1_, boff);
                bl[0] = lds_sw(tBl, nr, c0_, boff);
                bl[1] = lds_sw(tBl, nr, c1_, boff);
#pragma unroll
                for (int mt = 0; mt < 2; ++mt) {
                    mma16816(acc[mt][nt], ah[mt], bh);
                    mma16816(acc[mt][nt], ah[mt], bl);
                    mma16816(acc[mt][nt], al[mt], bh);
                }
            }
        }
        __syncthreads();   // all warps done with this chunk before restaging
    }

    // epilogue: fragment layout c0,c1 -> (row, col..col+1); c2,c3 -> (row+8, ..)
#pragma unroll
    for (int mt = 0; mt < 2; ++mt) {
        const int row = m0 + wm * 32 + mt * 16 + quad;
#pragma unroll
        for (int nt = 0; nt < 8; ++nt) {
            const int col = n0 + wn * 64 + nt * 8 + tq * 2;
            const float b0 = bias[col], b1 = bias[col + 1];
            float2 v0, v1;
            v0.x = acc[mt][nt][0] + b0; v0.y = acc[mt][nt][1] + b1;
            v1.x = acc[mt][nt][2] + b0; v1.y = acc[mt][nt][3] + b1;
            *(float2*)(Cc + (size_t)row * Ntot + col) = v0;
            *(float2*)(Cc + (size_t)(row + 8) * Ntot + col) = v1;
        }
    }
}

// ---------------------------------------------------------------------------
// Axial attention logits + softmax. Row and col modes fused in one launch:
// blockIdx.y == 0 -> row attn -> outA; ==1 -> col attn -> outB.
// ---------------------------------------------------------------------------
__global__ __launch_bounds__(256) void axial_logits_softmax(
    const float* __restrict__ qkv, float* __restrict__ outA,
    float* __restrict__ outB)
{
    const int bh = blockIdx.x;
    const int colmode = blockIdx.y;
    const int b = bh >> 3, h = bh & 7;
    const float* qbase = qkv + (size_t)b * NN * (3 * CC) + h * 64;

    __shared__ float Qs[64][65];
    __shared__ float Ks[64][65];

    const int tid = threadIdx.x;
    const int tx = tid & 15;
    const int ty = tid >> 4;

    float acc[4][4] = {};

    for (int chunk = 0; chunk < 64; ++chunk) {
#pragma unroll
        for (int p = 0; p < 4; ++p) {
            int row = ty + p * 16;
            int token = colmode ? (chunk * 64 + row) : (row * 64 + chunk);
            const float* qp = qbase + (size_t)token * (3 * CC) + tx * 4;
            float4 q4 = *(const float4*)qp;
            float4 k4 = *(const float4*)(qp + CC);
            Qs[row][tx * 4 + 0] = q4.x; Qs[row][tx * 4 + 1] = q4.y;
            Qs[row][tx * 4 + 2] = q4.z; Qs[row][tx * 4 + 3] = q4.w;
            Ks[row][tx * 4 + 0] = k4.x; Ks[row][tx * 4 + 1] = k4.y;
            Ks[row][tx * 4 + 2] = k4.z; Ks[row][tx * 4 + 3] = k4.w;
        }
        __syncthreads();
#pragma unroll 16
        for (int k = 0; k < 64; ++k) {
            float qf[4], kf[4];
#pragma unroll
            for (int i = 0; i < 4; ++i) qf[i] = Qs[ty * 4 + i][k];
#pragma unroll
            for (int j = 0; j < 4; ++j) kf[j] = Ks[tx * 4 + j][k];
#pragma unroll
            for (int i = 0; i < 4; ++i)
#pragma unroll
                for (int j = 0; j < 4; ++j)
                    acc[i][j] += qf[i] * kf[j];
        }
        __syncthreads();
    }

#pragma unroll
    for (int i = 0; i < 4; ++i)
#pragma unroll
        for (int j = 0; j < 4; ++j)
            Qs[ty * 4 + i][tx * 4 + j] = acc[i][j] * kSCALE;
    __syncthreads();

    const int warp = tid >> 5, lane = tid & 31;
    float* ob = (colmode ? outB : outA) + (size_t)bh * 4096;
    for (int r = warp; r < 64; r += 8) {
        float v0 = Qs[r][lane], v1 = Qs[r][lane + 32];
        float m = fmaxf(v0, v1);
#pragma unroll
        for (int o = 16; o > 0; o >>= 1)
            m = fmaxf(m, __shfl_xor_sync(0xffffffffu, m, o));
        float e0 = __expf(v0 - m), e1 = __expf(v1 - m);
        float s = e0 + e1;
#pragma unroll
        for (int o = 16; o > 0; o >>= 1)
            s += __shfl_xor_sync(0xffffffffu, s, o);
        float inv = 1.0f / s;
        ob[r * 64 + lane] = e0 * inv;
        ob[r * 64 + lane + 32] = e1 * inv;
    }
}

// ---------------------------------------------------------------------------
// Transpose V: qkv v-part [token, h*64+c] -> Vt[bh][c][t][w]
// ---------------------------------------------------------------------------
__global__ __launch_bounds__(256) void transpose_v(
    const float* __restrict__ qkv, float* __restrict__ Vt)
{
    const int t = blockIdx.x;
    const int bh = blockIdx.y;
    const int b = bh >> 3, h = bh & 7;
    __shared__ float tile[64][65];
    const int tid = threadIdx.x;
    const int tx = tid & 15, ty = tid >> 4;

    const float* vbase = qkv + (size_t)b * NN * (3 * CC) + 2 * CC + h * 64;
#pragma unroll
    for (int p = 0; p < 4; ++p) {
        int w = ty + p * 16;
        float4 v4 = *(const float4*)(vbase + (size_t)(t * 64 + w) * (3 * CC) + tx * 4);
        tile[w][tx * 4 + 0] = v4.x; tile[w][tx * 4 + 1] = v4.y;
        tile[w][tx * 4 + 2] = v4.z; tile[w][tx * 4 + 3] = v4.w;
    }
    __syncthreads();

    float* obase = Vt + (size_t)bh * 64 * 4096 + t * 64;
#pragma unroll
    for (int p = 0; p < 4; ++p) {
        int c = ty + p * 16;
        float4 o;
        o.x = tile[tx * 4 + 0][c];
        o.y = tile[tx * 4 + 1][c];
        o.z = tile[tx * 4 + 2][c];
        o.w = tile[tx * 4 + 3][c];
        *(float4*)(obase + (size_t)c * 4096 + tx * 4) = o;
    }
}

// ---------------------------------------------------------------------------
// Coupled combine: one block per (c, bh).
// ---------------------------------------------------------------------------
__global__ __launch_bounds__(256) void combine_kernel(
    const float* __restrict__ Abuf, const float* __restrict__ Bmbuf,
    const float* __restrict__ Vt, float* __restrict__ attnT)
{
    extern __shared__ float sm[];
    float (*As_)[65] = reinterpret_cast<float (*)[65]>(sm);
    float (*Bs_)[65] = reinterpret_cast<float (*)[65]>(sm + 64 * 65);
    float (*Vs)[65]  = reinterpret_cast<float (*)[65]>(sm + 2 * 64 * 65);
    float (*Ts)[65]  = reinterpret_cast<float (*)[65]>(sm + 3 * 64 * 65);

    const int c = blockIdx.x;
    const int bh = blockIdx.y;
    const int tid = threadIdx.x;
    const int tx = tid & 15, ty = tid >> 4;

    const float* ab = Abuf + (size_t)bh * 4096;
    const float* bb = Bmbuf + (size_t)bh * 4096;
    const float* vb = Vt + ((size_t)bh * 64 + c) * 4096;

#pragma unroll
    for (int p = 0; p < 4; ++p) {
        int row = ty + p * 16;
        float4 a4 = *(const float4*)(ab + row * 64 + tx * 4);
        float4 b4 = *(const float4*)(bb + row * 64 + tx * 4);
        float4 v4 = *(const float4*)(vb + row * 64 + tx * 4);
        As_[row][tx * 4 + 0] = a4.x; As_[row][tx * 4 + 1] = a4.y;
        As_[row][tx * 4 + 2] = a4.z; As_[row][tx * 4 + 3] = a4.w;
        Bs_[row][tx * 4 + 0] = b4.x; Bs_[row][tx * 4 + 1] = b4.y;
        Bs_[row][tx * 4 + 2] = b4.z; Bs_[row][tx * 4 + 3] = b4.w;
        Vs[row][tx * 4 + 0] = v4.x; Vs[row][tx * 4 + 1] = v4.y;
        Vs[row][tx * 4 + 2] = v4.z; Vs[row][tx * 4 + 3] = v4.w;
    }
    __syncthreads();

    {
        float acc[4][4] = {};
#pragma unroll 16
        for (int w = 0; w < 64; ++w) {
            float vf[4], bf[4];
#pragma unroll
            for (int i = 0; i < 4; ++i) vf[i] = Vs[ty * 4 + i][w];
#pragma unroll
            for (int j = 0; j < 4; ++j) bf[j] = Bs_[tx * 4 + j][w];
#pragma unroll
            for (int i = 0; i < 4; ++i)
#pragma unroll
                for (int j = 0; j < 4; ++j)
                    acc[i][j] += vf[i] * bf[j];
        }
#pragma unroll
        for (int i = 0; i < 4; ++i)
#pragma unroll
            for (int j = 0; j < 4; ++j)
                Ts[ty * 4 + i][tx * 4 + j] = acc[i][j];
    }
    __syncthreads();

    float acc[4][4] = {};
#pragma unroll 16
    for (int j = 0; j < 64; ++j) {
        float af[4], tf[4];
#pragma unroll
        for (int i = 0; i < 4; ++i) af[i] = As_[ty * 4 + i][j];
#pragma unroll
        for (int jj = 0; jj < 4; ++jj) tf[jj] = Ts[j][tx * 4 + jj];
#pragma unroll
        for (int i = 0; i < 4; ++i)
#pragma unroll
            for (int jj = 0; jj < 4; ++jj)
                acc[i][jj] += af[i] * tf[jj];
    }

    float* ob = attnT + ((size_t)bh * 64 + c) * 4096;
#pragma unroll
    for (int i = 0; i < 4; ++i) {
        float4 o;
        o.x = acc[i][0]; o.y = acc[i][1]; o.z = acc[i][2]; o.w = acc[i][3];
        *(float4*)(ob + (ty * 4 + i) * 64 + tx * 4) = o;
    }
}

// ---------------------------------------------------------------------------
extern "C" void kernel_launch(void* const* d_in, const int* in_sizes, int n_in,
                              void* d_out, int out_size)
{
    const float* x     = (const float*)d_in[0];
    const float* Wqkv  = (const float*)d_in[1];
    const float* bqkv  = (const float*)d_in[2];
    const float* Wproj = (const float*)d_in[3];
    const float* bproj = (const float*)d_in[4];
    float* out = (float*)d_out;

    float *qkv, *Ab, *Bmb, *Vt, *attnT;
    __nv_bfloat16 *Xh, *Xl, *WqTh, *WqTl, *WpTh, *WpTl;
    cudaGetSymbolAddress((void**)&qkv, g_qkv);
    cudaGetSymbolAddress((void**)&Ab, g_A);
    cudaGetSymbolAddress((void**)&Bmb, g_Bm);
    cudaGetSymbolAddress((void**)&Vt, g_Vt);
    cudaGetSymbolAddress((void**)&attnT, g_attnT);
    cudaGetSymbolAddress((void**)&Xh, g_Xh);
    cudaGetSymbolAddress((void**)&Xl, g_Xl);
    cudaGetSymbolAddress((void**)&WqTh, g_WqTh);
    cudaGetSymbolAddress((void**)&WqTl, g_WqTl);
    cudaGetSymbolAddress((void**)&WpTh, g_WpTh);
    cudaGetSymbolAddress((void**)&WpTl, g_WpTl);

    // host-side attribute sets (capture-safe; proven)
    cudaFuncSetAttribute(gemm_bf16x3, cudaFuncAttributeMaxDynamicSharedMemorySize,
                         GEMM_SMEM_BYTES);
    cudaFuncSetAttribute(combine_kernel, cudaFuncAttributeMaxDynamicSharedMemorySize,
                         4 * 64 * 65 * sizeof(float));

    // 0. split inputs to bf16 hi/lo
    split_f32<<<(BB * NN * CC / 4 + 255) / 256, 256>>>(x, Xh, Xl, BB * NN * CC / 4);
    split_transpose_w<<<dim3(1536 / 32, 512 / 32), dim3(32, 8)>>>(Wqkv, WqTh, WqTl, 1536);
    split_transpose_w<<<dim3(512 / 32, 512 / 32), dim3(32, 8)>>>(Wproj, WpTh, WpTl, 512);

    // 1. QKV projection on tensor cores: [65536,512] x [512,1536]
    gemm_bf16x3<<<dim3(1536 / 128, (BB * NN) / 128), 256, GEMM_SMEM_BYTES>>>(
        Xh, Xl, WqTh, WqTl, bqkv, qkv, 1536);

    // 2+3. axial attentions (row + col fused in one launch), softmaxed
    axial_logits_softmax<<<dim3(BB * HH, 2), 256>>>(qkv, Ab, Bmb);

    // 4. transpose V to channel-major
    transpose_v<<<dim3(64, BB * HH), 256>>>(qkv, Vt);

    // 5. coupled combine -> attnT [B, C, N]
    combine_kernel<<<dim3(64, BB * HH), 256, 4 * 64 * 65 * sizeof(float)>>>(Ab, Bmb, Vt, attnT);

    // 6. split+transpose attn output to token-major bf16 (reuse Xh/Xl)
    split_transpose_attn<<<dim3(NN / 32, CC / 32, BB), dim3(32, 8)>>>(attnT, Xh, Xl);

    // 7. projection on tensor cores: [65536,512] x [512,512]
    gemm_bf16x3<<<dim3(512 / 128, (BB * NN) / 128), 256, GEMM_SMEM_BYTES>>>(
        Xh, Xl, WpTh, WpTl, bproj, out, 512);
}